// round 5
// baseline (speedup 1.0000x reference)
#include <cuda_runtime.h>
#include <cstdint>

#define DIM 128
#define NMAX 50000

// Scratch (no cudaMalloc allowed)
__device__ float g_M[(size_t)NMAX * DIM];    // msg_lin(X)
__device__ float g_agg[(size_t)NMAX * DIM];  // (1+eps)*X + scatter-add
__device__ float g_Wt_msg[DIM * DIM];        // msg_w transposed: [f][g]
__device__ float g_Wt_lin[DIM * DIM];        // lin_w transposed: [f][g]
__device__ int   g_is64;

// ---------------------------------------------------------------------------
// Detect whether edge_index is int64 or int32. Node ids < 50000 < 2^31, so
// for little-endian int64 every odd 32-bit word of the first 128 entries is
// zero. For int32 random node ids the odds of 128 consecutive zeros are ~0.
// ---------------------------------------------------------------------------
__global__ void detect_kernel(const unsigned* __restrict__ e) {
    int is64 = 1;
    for (int i = 1; i < 256; i += 2) {
        if (e[i] != 0u) { is64 = 0; break; }
    }
    g_is64 = is64;
}

// ---------------------------------------------------------------------------
// One-time 128x128 transpose of both weight matrices (W[g][f] -> Wt[f][g]),
// so every GEMM CTA can load W coalesced and store to smem conflict-free.
// Standard 32x32 smem tile with +1 pad. grid=(4,4,2), block=(32,8).
// ---------------------------------------------------------------------------
__global__ void transpose_w_kernel(const float* __restrict__ W_msg,
                                   const float* __restrict__ W_lin)
{
    __shared__ float tile[32][33];
    const float* W  = blockIdx.z ? W_lin : W_msg;
    float*       Wt = blockIdx.z ? g_Wt_lin : g_Wt_msg;

    int tx = threadIdx.x, ty = threadIdx.y;
    int x = blockIdx.x * 32 + tx;      // f (contiguous in W)
    int y = blockIdx.y * 32 + ty;      // g
    #pragma unroll
    for (int j = 0; j < 32; j += 8)
        tile[ty + j][tx] = W[(y + j) * DIM + x];
    __syncthreads();
    int x2 = blockIdx.y * 32 + tx;     // g (contiguous in Wt)
    int y2 = blockIdx.x * 32 + ty;     // f
    #pragma unroll
    for (int j = 0; j < 32; j += 8)
        Wt[(y2 + j) * DIM + x2] = tile[tx][ty + j];
}

// ---------------------------------------------------------------------------
// C[n,g] = sum_f A[n,f] * Wt[f,g] + bias[g]      (optionally relu)
// Tile: 64 rows x 128 cols per 128-thread block; 8x8 microtile per thread.
// Wt (pre-transposed, [f][g]) loaded coalesced, stored to smem with row
// stride 132 (pad) -> conflict-free STS.128 and conflict-free mainloop LDS.
// FUSE_AGG: additionally writes agg[n,:] = (1+eps)*A[n,:]  (A==X here).
// smem/CTA = (128*132 + 64*128)*4 = 98 KB -> 2 CTAs/SM.
// ---------------------------------------------------------------------------
template <bool FUSE_AGG, bool RELU>
__global__ __launch_bounds__(128)
void gemm_kernel(const float* __restrict__ A,
                 const float* __restrict__ Wt_g,
                 const float* __restrict__ bias,
                 float* __restrict__ C,
                 float* __restrict__ agg,
                 const float* __restrict__ eps_ptr,
                 int N)
{
    extern __shared__ float smem[];
    float* Wt = smem;                 // [128][132]
    float* Xs = smem + 128 * 132;     // [64][128]

    const int tid = threadIdx.x;
    const int row0 = blockIdx.x * 64;

    // Load pre-transposed W: coalesced LDG.128, conflict-free STS.128.
    #pragma unroll 8
    for (int i = tid; i < 128 * 32; i += 128) {
        int f = i >> 5, g4 = i & 31;
        float4 v = *(const float4*)(Wt_g + f * DIM + g4 * 4);
        *(float4*)(Wt + f * 132 + g4 * 4) = v;
    }

    // Load X tile (64 rows x 128), zero-pad out-of-range rows
    #pragma unroll 4
    for (int idx = tid; idx < 64 * 32; idx += 128) {
        int r = idx >> 5, c4 = idx & 31;
        float4 v = make_float4(0.f, 0.f, 0.f, 0.f);
        if (row0 + r < N)
            v = *(const float4*)(A + (size_t)(row0 + r) * DIM + c4 * 4);
        *(float4*)(Xs + r * DIM + c4 * 4) = v;
    }
    __syncthreads();

    const int warp = tid >> 5, lane = tid & 31;
    const int wrow = warp * 16 + (lane >> 4) * 8;   // 8 rows per thread
    const int c0   = (lane & 15) * 8;               // 8 cols per thread

    float acc[8][8];
    #pragma unroll
    for (int i = 0; i < 8; i++)
        #pragma unroll
        for (int j = 0; j < 8; j++) acc[i][j] = 0.f;

    #pragma unroll 2
    for (int k = 0; k < 128; k += 4) {
        float4 xv[8];
        #pragma unroll
        for (int i = 0; i < 8; i++)
            xv[i] = *(float4*)&Xs[(wrow + i) * DIM + k];
        #pragma unroll
        for (int kk = 0; kk < 4; kk++) {
            float4 wa = *(float4*)&Wt[(k + kk) * 132 + c0];
            float4 wb = *(float4*)&Wt[(k + kk) * 132 + c0 + 4];
            #pragma unroll
            for (int i = 0; i < 8; i++) {
                float xs = (&xv[i].x)[kk];
                acc[i][0] += xs * wa.x; acc[i][1] += xs * wa.y;
                acc[i][2] += xs * wa.z; acc[i][3] += xs * wa.w;
                acc[i][4] += xs * wb.x; acc[i][5] += xs * wb.y;
                acc[i][6] += xs * wb.z; acc[i][7] += xs * wb.w;
            }
        }
    }

    float bl[8];
    #pragma unroll
    for (int j = 0; j < 8; j++) bl[j] = bias[c0 + j];

    #pragma unroll
    for (int i = 0; i < 8; i++) {
        int r = row0 + wrow + i;
        if (r < N) {
            float4 o0, o1;
            o0.x = acc[i][0] + bl[0]; o0.y = acc[i][1] + bl[1];
            o0.z = acc[i][2] + bl[2]; o0.w = acc[i][3] + bl[3];
            o1.x = acc[i][4] + bl[4]; o1.y = acc[i][5] + bl[5];
            o1.z = acc[i][6] + bl[6]; o1.w = acc[i][7] + bl[7];
            if (RELU) {
                o0.x = fmaxf(o0.x, 0.f); o0.y = fmaxf(o0.y, 0.f);
                o0.z = fmaxf(o0.z, 0.f); o0.w = fmaxf(o0.w, 0.f);
                o1.x = fmaxf(o1.x, 0.f); o1.y = fmaxf(o1.y, 0.f);
                o1.z = fmaxf(o1.z, 0.f); o1.w = fmaxf(o1.w, 0.f);
            }
            *(float4*)(C + (size_t)r * DIM + c0)     = o0;
            *(float4*)(C + (size_t)r * DIM + c0 + 4) = o1;
        }
    }

    if (FUSE_AGG) {
        float s = 1.0f + *eps_ptr;
        #pragma unroll 4
        for (int idx = tid; idx < 64 * 32; idx += 128) {
            int r = idx >> 5, c4 = idx & 31;
            if (row0 + r < N) {
                float4 v = *(float4*)(Xs + r * DIM + c4 * 4);
                v.x *= s; v.y *= s; v.z *= s; v.w *= s;
                *(float4*)(agg + (size_t)(row0 + r) * DIM + c4 * 4) = v;
            }
        }
    }
}

// ---------------------------------------------------------------------------
// One warp per edge: gather M[dst] (float4/lane) and reduce into agg[src]
// with red.global.add.v4.f32 (16B L2-side fp32 reductions). Edge-id loads are
// warp-uniform (broadcast, 1 request).
// ---------------------------------------------------------------------------
__global__ __launch_bounds__(512)
void scatter_kernel(const void* __restrict__ eidx, int E)
{
    int t = blockIdx.x * blockDim.x + threadIdx.x;
    int e = t >> 5;
    if (e >= E) return;
    int lane = t & 31;

    int src, dst;
    if (g_is64) {
        const long long* p = (const long long*)eidx;
        src = (int)p[e];
        dst = (int)p[(size_t)E + e];
    } else {
        const int* p = (const int*)eidx;
        src = p[e];
        dst = p[E + e];
    }

    const float4 m = *(const float4*)(g_M + (size_t)dst * DIM + lane * 4);
    float* a = g_agg + (size_t)src * DIM + lane * 4;
    asm volatile("red.global.add.v4.f32 [%0], {%1, %2, %3, %4};"
                 :: "l"(a), "f"(m.x), "f"(m.y), "f"(m.z), "f"(m.w)
                 : "memory");
}

// ---------------------------------------------------------------------------
extern "C" void kernel_launch(void* const* d_in, const int* in_sizes, int n_in,
                              void* d_out, int out_size)
{
    const float* X     = (const float*)d_in[0];
    const void*  eidx  = d_in[1];
    const float* eps   = (const float*)d_in[2];
    const float* msg_w = (const float*)d_in[3];
    const float* msg_b = (const float*)d_in[4];
    const float* lin_w = (const float*)d_in[5];
    const float* lin_b = (const float*)d_in[6];
    float* out = (float*)d_out;

    int N = in_sizes[0] / DIM;
    int E = in_sizes[1] / 2;

    float *Mptr, *aggptr, *WtMsg, *WtLin;
    cudaGetSymbolAddress((void**)&Mptr, g_M);
    cudaGetSymbolAddress((void**)&aggptr, g_agg);
    cudaGetSymbolAddress((void**)&WtMsg, g_Wt_msg);
    cudaGetSymbolAddress((void**)&WtLin, g_Wt_lin);

    const int smem = (128 * 132 + 64 * 128) * (int)sizeof(float);
    // Idempotent, called every time (no static guards per harness rules).
    cudaFuncSetAttribute(gemm_kernel<true, false>,
                         cudaFuncAttributeMaxDynamicSharedMemorySize, smem);
    cudaFuncSetAttribute(gemm_kernel<false, true>,
                         cudaFuncAttributeMaxDynamicSharedMemorySize, smem);
    cudaFuncSetAttribute(gemm_kernel<true, false>,
                         cudaFuncAttributePreferredSharedMemoryCarveout, 100);
    cudaFuncSetAttribute(gemm_kernel<false, true>,
                         cudaFuncAttributePreferredSharedMemoryCarveout, 100);

    // One-time transposes + dtype detection (independent, run up front).
    transpose_w_kernel<<<dim3(4, 4, 2), dim3(32, 8)>>>(msg_w, lin_w);
    detect_kernel<<<1, 1>>>((const unsigned*)eidx);

    int gb = (N + 63) / 64;
    // Phase 1: M = X @ msg_w^T + msg_b ; agg = (1+eps)*X
    gemm_kernel<true, false><<<gb, 128, smem>>>(X, WtMsg, msg_b, Mptr,
                                                aggptr, eps, N);
    // Phase 2: agg[src] += M[dst]
    int sblocks = (E * 32 + 511) / 512;
    scatter_kernel<<<sblocks, 512>>>(eidx, E);
    // Phase 3: out = relu(agg @ lin_w^T + lin_b)
    gemm_kernel<false, true><<<gb, 128, smem>>>(aggptr, WtLin, lin_b, out,
                                                nullptr, nullptr, N);
}

// round 7
// speedup vs baseline: 1.1224x; 1.1224x over previous
#include <cuda_runtime.h>
#include <cstdint>

#define DIM 128
#define NMAX 50000
#define EPW 4   // edges per warp iteration (MLP for the gather)

// Scratch (no cudaMalloc allowed)
__device__ float g_M[(size_t)NMAX * DIM];    // msg_lin(X)
__device__ float g_agg[(size_t)NMAX * DIM];  // (1+eps)*X + scatter-add
__device__ float g_Wt_msg[DIM * DIM];        // msg_w transposed: [f][g]
__device__ float g_Wt_lin[DIM * DIM];        // lin_w transposed: [f][g]
__device__ int   g_is64;

// ---------------------------------------------------------------------------
// Detect whether edge_index is int64 or int32. Node ids < 50000 < 2^31, so
// for little-endian int64 every odd 32-bit word of the first 128 entries is
// zero. For int32 random node ids the odds of 128 consecutive zeros are ~0.
// ---------------------------------------------------------------------------
__global__ void detect_kernel(const unsigned* __restrict__ e) {
    int is64 = 1;
    for (int i = 1; i < 256; i += 2) {
        if (e[i] != 0u) { is64 = 0; break; }
    }
    g_is64 = is64;
}

// ---------------------------------------------------------------------------
// One-time 128x128 transpose of both weight matrices (W[g][f] -> Wt[f][g]).
// ---------------------------------------------------------------------------
__global__ void transpose_w_kernel(const float* __restrict__ W_msg,
                                   const float* __restrict__ W_lin)
{
    __shared__ float tile[32][33];
    const float* W  = blockIdx.z ? W_lin : W_msg;
    float*       Wt = blockIdx.z ? g_Wt_lin : g_Wt_msg;

    int tx = threadIdx.x, ty = threadIdx.y;
    int x = blockIdx.x * 32 + tx;      // f (contiguous in W)
    int y = blockIdx.y * 32 + ty;      // g
    #pragma unroll
    for (int j = 0; j < 32; j += 8)
        tile[ty + j][tx] = W[(y + j) * DIM + x];
    __syncthreads();
    int x2 = blockIdx.y * 32 + tx;     // g (contiguous in Wt)
    int y2 = blockIdx.x * 32 + ty;     // f
    #pragma unroll
    for (int j = 0; j < 32; j += 8)
        Wt[(y2 + j) * DIM + x2] = tile[tx][ty + j];
}

// ---------------------------------------------------------------------------
// C[n,g] = sum_f A[n,f] * Wt[f,g] + bias[g]      (optionally relu)
// 64x128 tile, 128 threads, 8x8 microtile. Near fp32-FFMA roofline.
// ---------------------------------------------------------------------------
template <bool FUSE_AGG, bool RELU>
__global__ __launch_bounds__(128)
void gemm_kernel(const float* __restrict__ A,
                 const float* __restrict__ Wt_g,
                 const float* __restrict__ bias,
                 float* __restrict__ C,
                 float* __restrict__ agg,
                 const float* __restrict__ eps_ptr,
                 int N)
{
    extern __shared__ float smem[];
    float* Wt = smem;                 // [128][132]
    float* Xs = smem + 128 * 132;     // [64][128]

    const int tid = threadIdx.x;
    const int row0 = blockIdx.x * 64;

    // Load pre-transposed W: coalesced LDG.128, conflict-free STS.128.
    #pragma unroll 8
    for (int i = tid; i < 128 * 32; i += 128) {
        int f = i >> 5, g4 = i & 31;
        float4 v = *(const float4*)(Wt_g + f * DIM + g4 * 4);
        *(float4*)(Wt + f * 132 + g4 * 4) = v;
    }

    // Load X tile (64 rows x 128), zero-pad out-of-range rows
    #pragma unroll 4
    for (int idx = tid; idx < 64 * 32; idx += 128) {
        int r = idx >> 5, c4 = idx & 31;
        float4 v = make_float4(0.f, 0.f, 0.f, 0.f);
        if (row0 + r < N)
            v = *(const float4*)(A + (size_t)(row0 + r) * DIM + c4 * 4);
        *(float4*)(Xs + r * DIM + c4 * 4) = v;
    }
    __syncthreads();

    const int warp = tid >> 5, lane = tid & 31;
    const int wrow = warp * 16 + (lane >> 4) * 8;   // 8 rows per thread
    const int c0   = (lane & 15) * 8;               // 8 cols per thread

    float acc[8][8];
    #pragma unroll
    for (int i = 0; i < 8; i++)
        #pragma unroll
        for (int j = 0; j < 8; j++) acc[i][j] = 0.f;

    #pragma unroll 2
    for (int k = 0; k < 128; k += 4) {
        float4 xv[8];
        #pragma unroll
        for (int i = 0; i < 8; i++)
            xv[i] = *(float4*)&Xs[(wrow + i) * DIM + k];
        #pragma unroll
        for (int kk = 0; kk < 4; kk++) {
            float4 wa = *(float4*)&Wt[(k + kk) * 132 + c0];
            float4 wb = *(float4*)&Wt[(k + kk) * 132 + c0 + 4];
            #pragma unroll
            for (int i = 0; i < 8; i++) {
                float xs = (&xv[i].x)[kk];
                acc[i][0] += xs * wa.x; acc[i][1] += xs * wa.y;
                acc[i][2] += xs * wa.z; acc[i][3] += xs * wa.w;
                acc[i][4] += xs * wb.x; acc[i][5] += xs * wb.y;
                acc[i][6] += xs * wb.z; acc[i][7] += xs * wb.w;
            }
        }
    }

    float bl[8];
    #pragma unroll
    for (int j = 0; j < 8; j++) bl[j] = bias[c0 + j];

    #pragma unroll
    for (int i = 0; i < 8; i++) {
        int r = row0 + wrow + i;
        if (r < N) {
            float4 o0, o1;
            o0.x = acc[i][0] + bl[0]; o0.y = acc[i][1] + bl[1];
            o0.z = acc[i][2] + bl[2]; o0.w = acc[i][3] + bl[3];
            o1.x = acc[i][4] + bl[4]; o1.y = acc[i][5] + bl[5];
            o1.z = acc[i][6] + bl[6]; o1.w = acc[i][7] + bl[7];
            if (RELU) {
                o0.x = fmaxf(o0.x, 0.f); o0.y = fmaxf(o0.y, 0.f);
                o0.z = fmaxf(o0.z, 0.f); o0.w = fmaxf(o0.w, 0.f);
                o1.x = fmaxf(o1.x, 0.f); o1.y = fmaxf(o1.y, 0.f);
                o1.z = fmaxf(o1.z, 0.f); o1.w = fmaxf(o1.w, 0.f);
            }
            *(float4*)(C + (size_t)r * DIM + c0)     = o0;
            *(float4*)(C + (size_t)r * DIM + c0 + 4) = o1;
        }
    }

    if (FUSE_AGG) {
        float s = 1.0f + *eps_ptr;
        #pragma unroll 4
        for (int idx = tid; idx < 64 * 32; idx += 128) {
            int r = idx >> 5, c4 = idx & 31;
            if (row0 + r < N) {
                float4 v = *(float4*)(Xs + r * DIM + c4 * 4);
                v.x *= s; v.y *= s; v.z *= s; v.w *= s;
                *(float4*)(agg + (size_t)(row0 + r) * DIM + c4 * 4) = v;
            }
        }
    }
}

// ---------------------------------------------------------------------------
// Scatter v2: each warp processes EPW=4 edges per pass. All 4 gathers are
// issued back-to-back (independent LDG.128 -> MLP=4 outstanding), then the
// 4 RED.128 ops. Attacks the exposed L2-hit latency ncu showed (issue=22%).
// ---------------------------------------------------------------------------
__global__ __launch_bounds__(256)
void scatter_kernel(const void* __restrict__ eidx, int E)
{
    const int lane = threadIdx.x & 31;
    const int warp = blockIdx.x * (blockDim.x >> 5) + (threadIdx.x >> 5);
    const int e0 = warp * EPW;
    if (e0 >= E) return;

    int src[EPW], dst[EPW];
    if (g_is64) {
        const long long* p = (const long long*)eidx;
        #pragma unroll
        for (int j = 0; j < EPW; j++) {
            int e = e0 + j;
            if (e < E) { src[j] = (int)p[e]; dst[j] = (int)p[(size_t)E + e]; }
            else       { src[j] = -1;        dst[j] = 0; }
        }
    } else {
        const int* p = (const int*)eidx;
        #pragma unroll
        for (int j = 0; j < EPW; j++) {
            int e = e0 + j;
            if (e < E) { src[j] = p[e]; dst[j] = p[E + e]; }
            else       { src[j] = -1;   dst[j] = 0; }
        }
    }

    // Batched gathers: 4 independent LDG.128 in flight per thread.
    float4 m[EPW];
    #pragma unroll
    for (int j = 0; j < EPW; j++)
        m[j] = *(const float4*)(g_M + (size_t)dst[j] * DIM + lane * 4);

    #pragma unroll
    for (int j = 0; j < EPW; j++) {
        if (src[j] >= 0) {
            float* a = g_agg + (size_t)src[j] * DIM + lane * 4;
            asm volatile("red.global.add.v4.f32 [%0], {%1, %2, %3, %4};"
                         :: "l"(a), "f"(m[j].x), "f"(m[j].y),
                            "f"(m[j].z), "f"(m[j].w)
                         : "memory");
        }
    }
}

// ---------------------------------------------------------------------------
extern "C" void kernel_launch(void* const* d_in, const int* in_sizes, int n_in,
                              void* d_out, int out_size)
{
    const float* X     = (const float*)d_in[0];
    const void*  eidx  = d_in[1];
    const float* eps   = (const float*)d_in[2];
    const float* msg_w = (const float*)d_in[3];
    const float* msg_b = (const float*)d_in[4];
    const float* lin_w = (const float*)d_in[5];
    const float* lin_b = (const float*)d_in[6];
    float* out = (float*)d_out;

    int N = in_sizes[0] / DIM;
    int E = in_sizes[1] / 2;

    float *Mptr, *aggptr, *WtMsg, *WtLin;
    cudaGetSymbolAddress((void**)&Mptr, g_M);
    cudaGetSymbolAddress((void**)&aggptr, g_agg);
    cudaGetSymbolAddress((void**)&WtMsg, g_Wt_msg);
    cudaGetSymbolAddress((void**)&WtLin, g_Wt_lin);

    const int smem = (128 * 132 + 64 * 128) * (int)sizeof(float);
    cudaFuncSetAttribute(gemm_kernel<true, false>,
                         cudaFuncAttributeMaxDynamicSharedMemorySize, smem);
    cudaFuncSetAttribute(gemm_kernel<false, true>,
                         cudaFuncAttributeMaxDynamicSharedMemorySize, smem);
    cudaFuncSetAttribute(gemm_kernel<true, false>,
                         cudaFuncAttributePreferredSharedMemoryCarveout, 100);
    cudaFuncSetAttribute(gemm_kernel<false, true>,
                         cudaFuncAttributePreferredSharedMemoryCarveout, 100);

    // One-time transposes + dtype detection (independent, run up front).
    transpose_w_kernel<<<dim3(4, 4, 2), dim3(32, 8)>>>(msg_w, lin_w);
    detect_kernel<<<1, 1>>>((const unsigned*)eidx);

    int gb = (N + 63) / 64;
    // Phase 1: M = X @ msg_w^T + msg_b ; agg = (1+eps)*X
    gemm_kernel<true, false><<<gb, 128, smem>>>(X, WtMsg, msg_b, Mptr,
                                                aggptr, eps, N);
    // Phase 2: agg[src] += M[dst]   (8 warps/block, EPW edges/warp)
    int warps_needed = (E + EPW - 1) / EPW;
    int sblocks = (warps_needed + 7) / 8;
    scatter_kernel<<<sblocks, 256>>>(eidx, E);
    // Phase 3: out = relu(agg @ lin_w^T + lin_b)
    gemm_kernel<false, true><<<gb, 128, smem>>>(aggptr, WtLin, lin_b, out,
                                                nullptr, nullptr, N);
}